// round 3
// baseline (speedup 1.0000x reference)
#include <cuda_runtime.h>
#include <math.h>

#define BATCH 8
#define DIM   192
#define C3    576
#define HID   576
#define HEADS 4
#define CH    48
#define HW    16384
#define EPSLN 1e-5f

// ---------------- scratch (device globals; allocation-free) ----------------
__device__ float g_bufA[(size_t)BATCH * C3 * HW];   // 302 MB
__device__ float g_bufB[(size_t)BATCH * C3 * HW];   // 302 MB
__device__ float g_bufC[(size_t)BATCH * DIM * HW];  // 100 MB
__device__ float g_inv[BATCH * 2 * DIM];            // 1/||q||, 1/||k|| per row
__device__ float g_attnp[BATCH * HEADS * 16 * CH * CH]; // split-K partials
__device__ float g_attn[BATCH * HEADS * CH * CH];       // softmaxed attn

// ---------------- LayerNorm over channel dim ----------------
__global__ void ln_kernel(const float* __restrict__ x, const float* __restrict__ w,
                          const float* __restrict__ b, float* __restrict__ y) {
    int p  = blockIdx.x * 256 + threadIdx.x;
    int bb = blockIdx.y;
    const float* xp = x + (size_t)bb * DIM * HW + p;
    float s = 0.f, ss = 0.f;
    #pragma unroll 4
    for (int c = 0; c < DIM; c++) { float v = xp[(size_t)c * HW]; s += v; ss += v * v; }
    float mu  = s * (1.f / DIM);
    float var = ss * (1.f / DIM) - mu * mu;
    float inv = rsqrtf(var + EPSLN);
    float* yp = y + (size_t)bb * DIM * HW + p;
    #pragma unroll 4
    for (int c = 0; c < DIM; c++)
        yp[(size_t)c * HW] = (xp[(size_t)c * HW] - mu) * inv * w[c] + b[c];
}

// ---------------- 1x1 conv = GEMM: Y[m,n] = sum_k W[m,k] X[k,n] ----------------
// mode 0: +bias, mode 1: +bias then exact GELU, mode 2: +bias + residual R
#define BM 64
#define BN 64
#define BKK 16
__global__ void gemm1x1(const float* __restrict__ Wt, const float* __restrict__ bias,
                        const float* __restrict__ X, float* __restrict__ Y,
                        int M, int K, int mode, const float* __restrict__ R) {
    __shared__ float As[BKK][BM + 1];
    __shared__ float Bs[BKK][BN];
    int bz = blockIdx.z;
    int m0 = blockIdx.y * BM;
    int n0 = blockIdx.x * BN;
    const float* Xb = X + (size_t)bz * K * HW;
    int tid = threadIdx.x;
    int tx = tid & 15, ty = tid >> 4;
    float acc[4][4] = {};
    for (int k0 = 0; k0 < K; k0 += BKK) {
        for (int i = tid; i < BM * BKK; i += 256) {
            int m = i >> 4, k = i & 15;
            As[k][m] = Wt[(size_t)(m0 + m) * K + k0 + k];
        }
        for (int i = tid; i < BKK * BN; i += 256) {
            int k = i >> 6, n = i & 63;
            Bs[k][n] = Xb[(size_t)(k0 + k) * HW + n0 + n];
        }
        __syncthreads();
        #pragma unroll
        for (int kk = 0; kk < BKK; ++kk) {
            float4 bv = *(const float4*)&Bs[kk][tx * 4];
            float a0 = As[kk][ty * 4 + 0];
            float a1 = As[kk][ty * 4 + 1];
            float a2 = As[kk][ty * 4 + 2];
            float a3 = As[kk][ty * 4 + 3];
            acc[0][0] += a0 * bv.x; acc[0][1] += a0 * bv.y; acc[0][2] += a0 * bv.z; acc[0][3] += a0 * bv.w;
            acc[1][0] += a1 * bv.x; acc[1][1] += a1 * bv.y; acc[1][2] += a1 * bv.z; acc[1][3] += a1 * bv.w;
            acc[2][0] += a2 * bv.x; acc[2][1] += a2 * bv.y; acc[2][2] += a2 * bv.z; acc[2][3] += a2 * bv.w;
            acc[3][0] += a3 * bv.x; acc[3][1] += a3 * bv.y; acc[3][2] += a3 * bv.z; acc[3][3] += a3 * bv.w;
        }
        __syncthreads();
    }
    float* Yb = Y + (size_t)bz * M * HW;
    const float* Rb = (mode == 2) ? (R + (size_t)bz * M * HW) : nullptr;
    #pragma unroll
    for (int i = 0; i < 4; i++) {
        int m = m0 + ty * 4 + i;
        float bv = bias[m];
        int n = n0 + tx * 4;
        size_t off = (size_t)m * HW + n;
        float v0 = acc[i][0] + bv, v1 = acc[i][1] + bv, v2 = acc[i][2] + bv, v3 = acc[i][3] + bv;
        if (mode == 1) {
            v0 = 0.5f * v0 * (1.f + erff(v0 * 0.70710678118654752f));
            v1 = 0.5f * v1 * (1.f + erff(v1 * 0.70710678118654752f));
            v2 = 0.5f * v2 * (1.f + erff(v2 * 0.70710678118654752f));
            v3 = 0.5f * v3 * (1.f + erff(v3 * 0.70710678118654752f));
        } else if (mode == 2) {
            float4 rv = *(const float4*)&Rb[off];
            v0 += rv.x; v1 += rv.y; v2 += rv.z; v3 += rv.w;
        }
        *(float4*)&Yb[off] = make_float4(v0, v1, v2, v3);
    }
}

// ---------------- depthwise / grouped 3x3, pad 1 (ic = oc / div) ----------------
__global__ void dwconv3(const float* __restrict__ X, const float* __restrict__ Wt,
                        const float* __restrict__ bias, float* __restrict__ Y,
                        int Cin, int Cout, int div) {
    int p  = blockIdx.x * 256 + threadIdx.x;
    int oc = blockIdx.y;
    int bb = blockIdx.z;
    int xx = p & 127, yy = p >> 7;
    int ic = oc / div;
    const float* Xp = X + ((size_t)bb * Cin + ic) * HW;
    const float* wv = Wt + oc * 9;
    float s = bias[oc];
    #pragma unroll
    for (int dy = -1; dy <= 1; dy++) {
        int y2 = yy + dy;
        if ((unsigned)y2 >= 128u) continue;
        #pragma unroll
        for (int dx = -1; dx <= 1; dx++) {
            int x2 = xx + dx;
            if ((unsigned)x2 >= 128u) continue;
            s += wv[(dy + 1) * 3 + (dx + 1)] * Xp[y2 * 128 + x2];
        }
    }
    Y[((size_t)bb * Cout + oc) * HW + p] = s;
}

// ---------------- per-row inverse L2 norms of (q|k)+prompt ----------------
__global__ void norms_kernel(const float* __restrict__ QKV, const float* __restrict__ prompt) {
    int r  = blockIdx.x;  // 0..383: 0..191 = q rows, 192..383 = k rows
    int bb = blockIdx.y;
    int c = (r < DIM) ? r : (r - DIM);
    int base = (r < DIM) ? 0 : DIM;
    const float* Xp = QKV + ((size_t)bb * C3 + base + c) * HW;
    float pr = prompt[c];  // prompt[h*48+ch] == prompt[c]
    float s = 0.f;
    for (int n = threadIdx.x; n < HW; n += 256) { float v = Xp[n] + pr; s += v * v; }
    __shared__ float red[256];
    red[threadIdx.x] = s; __syncthreads();
    for (int st = 128; st > 0; st >>= 1) {
        if (threadIdx.x < st) red[threadIdx.x] += red[threadIdx.x + st];
        __syncthreads();
    }
    if (threadIdx.x == 0)
        g_inv[bb * 2 * DIM + r] = 1.f / fmaxf(sqrtf(red[0]), 1e-12f);
}

// ---------------- attn partials: q @ k^T over a 1024-col chunk ----------------
__global__ void attn_qk_kernel(const float* __restrict__ QKV, const float* __restrict__ prompt) {
    int chunk = blockIdx.x;  // 0..15
    int h = blockIdx.y, bb = blockIdx.z;
    __shared__ float qS[CH][65];
    __shared__ float kS[CH][65];
    int tid = threadIdx.x;
    int tx = tid & 15, ty = tid >> 4;
    float acc[3][3] = {};
    const float* Qb = QKV + ((size_t)bb * C3 + h * CH) * HW;
    const float* Kb = QKV + ((size_t)bb * C3 + DIM + h * CH) * HW;
    const float* iq = g_inv + bb * 2 * DIM + h * CH;
    const float* ik = g_inv + bb * 2 * DIM + DIM + h * CH;
    for (int sub = 0; sub < 16; sub++) {
        int n0 = chunk * 1024 + sub * 64;
        for (int i = tid; i < CH * 64; i += 256) {
            int c = i >> 6, n = i & 63;
            float pr = prompt[h * CH + c];
            qS[c][n] = (Qb[(size_t)c * HW + n0 + n] + pr) * iq[c];
            kS[c][n] = (Kb[(size_t)c * HW + n0 + n] + pr) * ik[c];
        }
        __syncthreads();
        #pragma unroll 8
        for (int n = 0; n < 64; n++) {
            float a0 = qS[ty * 3 + 0][n], a1 = qS[ty * 3 + 1][n], a2 = qS[ty * 3 + 2][n];
            float b0 = kS[tx * 3 + 0][n], b1 = kS[tx * 3 + 1][n], b2 = kS[tx * 3 + 2][n];
            acc[0][0] += a0 * b0; acc[0][1] += a0 * b1; acc[0][2] += a0 * b2;
            acc[1][0] += a1 * b0; acc[1][1] += a1 * b1; acc[1][2] += a1 * b2;
            acc[2][0] += a2 * b0; acc[2][1] += a2 * b1; acc[2][2] += a2 * b2;
        }
        __syncthreads();
    }
    float* out = g_attnp + (((size_t)(bb * HEADS + h)) * 16 + chunk) * CH * CH;
    #pragma unroll
    for (int i = 0; i < 3; i++)
        #pragma unroll
        for (int j = 0; j < 3; j++)
            out[(ty * 3 + i) * CH + tx * 3 + j] = acc[i][j];
}

// ---------------- reduce partials, temperature, row softmax ----------------
__global__ void softmax_kernel(const float* __restrict__ temperature) {
    int h = blockIdx.x, bb = blockIdx.y;
    __shared__ float sA[CH][CH];
    const float* P = g_attnp + ((size_t)(bb * HEADS + h)) * 16 * CH * CH;
    float t = temperature[h];
    for (int i = threadIdx.x; i < CH * CH; i += blockDim.x) {
        float s = 0.f;
        #pragma unroll
        for (int c2 = 0; c2 < 16; c2++) s += P[c2 * CH * CH + i];
        sA[i / CH][i % CH] = s * t;
    }
    __syncthreads();
    if (threadIdx.x < CH) {
        int r = threadIdx.x;
        float mx = -1e30f;
        for (int d = 0; d < CH; d++) mx = fmaxf(mx, sA[r][d]);
        float sum = 0.f;
        float e[CH];
        for (int d = 0; d < CH; d++) { e[d] = expf(sA[r][d] - mx); sum += e[d]; }
        float inv = 1.f / sum;
        float* O = g_attn + ((size_t)(bb * HEADS + h)) * CH * CH + r * CH;
        for (int d = 0; d < CH; d++) O[d] = e[d] * inv;
    }
}

// ---------------- out = attn @ (v + prompt) ----------------
__global__ void attn_v_kernel(const float* __restrict__ QKV, const float* __restrict__ prompt,
                              float* __restrict__ O) {
    int nb = blockIdx.x;  // 0..127 (128-col chunks)
    int h = blockIdx.y, bb = blockIdx.z;
    __shared__ float aS[CH][CH];
    __shared__ float vS[CH][128];
    int tid = threadIdx.x;  // 128 threads
    const float* A = g_attn + ((size_t)(bb * HEADS + h)) * CH * CH;
    for (int i = tid; i < CH * CH; i += 128) aS[i / CH][i % CH] = A[i];
    const float* Vb = QKV + ((size_t)bb * C3 + 2 * DIM + h * CH) * HW;
    int n0 = nb * 128;
    for (int i = tid; i < CH * 128; i += 128) {
        int d = i >> 7, n = i & 127;
        vS[d][n] = Vb[(size_t)d * HW + n0 + n] + prompt[h * CH + d];
    }
    __syncthreads();
    float acc[CH];
    #pragma unroll
    for (int c = 0; c < CH; c++) acc[c] = 0.f;
    int n = tid;
    for (int d = 0; d < CH; d++) {
        float vv = vS[d][n];
        #pragma unroll
        for (int c = 0; c < CH; c++) acc[c] += aS[c][d] * vv;
    }
    float* Ob = O + ((size_t)bb * DIM + h * CH) * HW + n0 + n;
    #pragma unroll
    for (int c = 0; c < CH; c++) Ob[(size_t)c * HW] = acc[c];
}

// ---------------- launch ----------------
extern "C" void kernel_launch(void* const* d_in, const int* in_sizes, int n_in,
                              void* d_out, int out_size) {
    const float* x        = (const float*)d_in[0];
    const float* ln1_w    = (const float*)d_in[1];
    const float* ln1_b    = (const float*)d_in[2];
    const float* qkv_w    = (const float*)d_in[3];
    const float* qkv_b    = (const float*)d_in[4];
    const float* qkv_dw_w = (const float*)d_in[5];
    const float* qkv_dw_b = (const float*)d_in[6];
    const float* temp     = (const float*)d_in[7];
    const float* prompt   = (const float*)d_in[8];
    const float* proj_w   = (const float*)d_in[9];
    const float* proj_b   = (const float*)d_in[10];
    const float* ln2_w    = (const float*)d_in[11];
    const float* ln2_b    = (const float*)d_in[12];
    const float* dw1_w    = (const float*)d_in[13];
    const float* dw1_b    = (const float*)d_in[14];
    const float* pm_w     = (const float*)d_in[15];
    const float* pm_b     = (const float*)d_in[16];
    const float* dw2_w    = (const float*)d_in[17];
    const float* dw2_b    = (const float*)d_in[18];
    const float* po_w     = (const float*)d_in[19];
    const float* po_b     = (const float*)d_in[20];
    float* out = (float*)d_out;

    float *bufA, *bufB, *bufC;
    cudaGetSymbolAddress((void**)&bufA, g_bufA);
    cudaGetSymbolAddress((void**)&bufB, g_bufB);
    cudaGetSymbolAddress((void**)&bufC, g_bufC);

    // 1) LN1: x -> bufC
    ln_kernel<<<dim3(HW / 256, BATCH), 256>>>(x, ln1_w, ln1_b, bufC);
    // 2) qkv 1x1 (192->576): bufC -> bufA
    gemm1x1<<<dim3(HW / BN, C3 / BM, BATCH), 256>>>(qkv_w, qkv_b, bufC, bufA, C3, DIM, 0, nullptr);
    // 3) qkv depthwise 3x3: bufA -> bufB
    dwconv3<<<dim3(HW / 256, C3, BATCH), 256>>>(bufA, qkv_dw_w, qkv_dw_b, bufB, C3, C3, 1);
    // 4) row norms of q,k (+prompt)
    norms_kernel<<<dim3(2 * DIM, BATCH), 256>>>(bufB, prompt);
    // 5) attn logits partials, softmax, out
    attn_qk_kernel<<<dim3(16, HEADS, BATCH), 256>>>(bufB, prompt);
    softmax_kernel<<<dim3(HEADS, BATCH), 256>>>(temp);
    attn_v_kernel<<<dim3(HW / 128, HEADS, BATCH), 128>>>(bufB, prompt, bufC);
    // 6) proj 1x1 (192->192) + residual x: -> d_out (= x2)
    gemm1x1<<<dim3(HW / BN, DIM / BM, BATCH), 256>>>(proj_w, proj_b, bufC, out, DIM, DIM, 2, x);
    // 7) LN2: d_out -> bufC
    ln_kernel<<<dim3(HW / 256, BATCH), 256>>>(out, ln2_w, ln2_b, bufC);
    // 8) grouped 3x3 (192->576, groups=192): bufC -> bufA
    dwconv3<<<dim3(HW / 256, HID, BATCH), 256>>>(bufC, dw1_w, dw1_b, bufA, DIM, HID, 3);
    // 9) pm 1x1 (576->576) + GELU: bufA -> bufB
    gemm1x1<<<dim3(HW / BN, HID / BM, BATCH), 256>>>(pm_w, pm_b, bufA, bufB, HID, HID, 1, nullptr);
    // 10) depthwise 3x3 on 576: bufB -> bufA
    dwconv3<<<dim3(HW / 256, HID, BATCH), 256>>>(bufB, dw2_w, dw2_b, bufA, HID, HID, 1);
    // 11) po 1x1 (576->192) + residual (in-place on d_out)
    gemm1x1<<<dim3(HW / BN, DIM / BM, BATCH), 256>>>(po_w, po_b, bufA, out, DIM, HID, 2, out);
}

// round 4
// speedup vs baseline: 2.3934x; 2.3934x over previous
#include <cuda_runtime.h>
#include <math.h>

#define BATCH 8
#define DIM   192
#define C3    576
#define HID   576
#define HEADS 4
#define CH    48
#define HW    16384
#define EPSLN 1e-5f

// ---------------- scratch (device globals; allocation-free) ----------------
__device__ float g_bufA[(size_t)BATCH * C3 * HW];   // 302 MB
__device__ float g_bufB[(size_t)BATCH * C3 * HW];   // 302 MB
__device__ float g_bufC[(size_t)BATCH * DIM * HW];  // 100 MB
__device__ float g_inv[BATCH * 2 * DIM];            // 1/||q||, 1/||k|| per row
__device__ float g_attnp[BATCH * HEADS * 16 * CH * CH]; // split-K partials
__device__ float g_attn[BATCH * HEADS * CH * CH];       // softmaxed attn

// ---------------- LayerNorm over channel dim ----------------
__global__ void ln_kernel(const float* __restrict__ x, const float* __restrict__ w,
                          const float* __restrict__ b, float* __restrict__ y) {
    int p  = blockIdx.x * 256 + threadIdx.x;
    int bb = blockIdx.y;
    const float* xp = x + (size_t)bb * DIM * HW + p;
    float s = 0.f, ss = 0.f;
    #pragma unroll 4
    for (int c = 0; c < DIM; c++) { float v = xp[(size_t)c * HW]; s += v; ss += v * v; }
    float mu  = s * (1.f / DIM);
    float var = ss * (1.f / DIM) - mu * mu;
    float inv = rsqrtf(var + EPSLN);
    float* yp = y + (size_t)bb * DIM * HW + p;
    #pragma unroll 4
    for (int c = 0; c < DIM; c++)
        yp[(size_t)c * HW] = (xp[(size_t)c * HW] - mu) * inv * w[c] + b[c];
}

// ---------------- tf32 tensor-core GEMM: Y[m,n] = sum_k W[m,k] X[k,n] ----------------
// Tile: BM=64, BN=256, BK=32. 256 threads = 8 warps (2 m x 4 n), warp tile 32x64.
// mma.sync m16n8k8 tf32. mode 0: +bias, 1: +bias+GELU, 2: +bias+residual.
#define GBM 64
#define GBN 256
#define GBK 32
#define APAD 4
#define BPAD 4

__device__ __forceinline__ unsigned f2tf(float f) {
    unsigned r; asm("cvt.rna.tf32.f32 %0, %1;" : "=r"(r) : "f"(f)); return r;
}

__global__ __launch_bounds__(256, 2)
void gemm_tc(const float* __restrict__ Wt, const float* __restrict__ bias,
             const float* __restrict__ X, float* __restrict__ Y,
             int M, int K, int mode, const float* __restrict__ R) {
    __shared__ unsigned As[GBM][GBK + APAD];
    __shared__ unsigned Bs[GBK][GBN + BPAD];

    int bz = blockIdx.z;
    int m0 = blockIdx.y * GBM;
    int n0 = blockIdx.x * GBN;
    const float* Xb = X + (size_t)bz * K * HW;

    int tid  = threadIdx.x;
    int warp = tid >> 5;
    int lane = tid & 31;
    int g = lane >> 2;      // groupID 0..7
    int t = lane & 3;       // thread-in-group 0..3
    int wm = warp >> 2;     // 0..1
    int wn = warp & 3;      // 0..3

    float acc[2][8][4];
    #pragma unroll
    for (int i = 0; i < 2; i++)
        #pragma unroll
        for (int j = 0; j < 8; j++)
            #pragma unroll
            for (int q = 0; q < 4; q++) acc[i][j][q] = 0.f;

    for (int k0 = 0; k0 < K; k0 += GBK) {
        // load A tile (64x32): 512 float4, 2 per thread
        #pragma unroll
        for (int i = 0; i < 2; i++) {
            int idx = tid + i * 256;
            int m = idx >> 3, k4 = (idx & 7) << 2;
            float4 v = *(const float4*)&Wt[(size_t)(m0 + m) * K + k0 + k4];
            As[m][k4 + 0] = f2tf(v.x); As[m][k4 + 1] = f2tf(v.y);
            As[m][k4 + 2] = f2tf(v.z); As[m][k4 + 3] = f2tf(v.w);
        }
        // load B tile (32x256): 2048 float4, 8 per thread
        #pragma unroll
        for (int i = 0; i < 8; i++) {
            int idx = tid + i * 256;
            int k = idx >> 6, n4 = (idx & 63) << 2;
            float4 v = *(const float4*)&Xb[(size_t)(k0 + k) * HW + n0 + n4];
            Bs[k][n4 + 0] = f2tf(v.x); Bs[k][n4 + 1] = f2tf(v.y);
            Bs[k][n4 + 2] = f2tf(v.z); Bs[k][n4 + 3] = f2tf(v.w);
        }
        __syncthreads();

        #pragma unroll
        for (int kk = 0; kk < GBK; kk += 8) {
            unsigned af[2][4], bf[8][2];
            #pragma unroll
            for (int im = 0; im < 2; im++) {
                int rb = wm * 32 + im * 16;
                af[im][0] = As[rb + g][kk + t];
                af[im][1] = As[rb + g + 8][kk + t];
                af[im][2] = As[rb + g][kk + t + 4];
                af[im][3] = As[rb + g + 8][kk + t + 4];
            }
            #pragma unroll
            for (int in = 0; in < 8; in++) {
                int cb = wn * 64 + in * 8 + g;
                bf[in][0] = Bs[kk + t][cb];
                bf[in][1] = Bs[kk + t + 4][cb];
            }
            #pragma unroll
            for (int im = 0; im < 2; im++)
                #pragma unroll
                for (int in = 0; in < 8; in++) {
                    asm volatile(
                        "mma.sync.aligned.m16n8k8.row.col.f32.tf32.tf32.f32 "
                        "{%0,%1,%2,%3}, {%4,%5,%6,%7}, {%8,%9}, {%0,%1,%2,%3};"
                        : "+f"(acc[im][in][0]), "+f"(acc[im][in][1]),
                          "+f"(acc[im][in][2]), "+f"(acc[im][in][3])
                        : "r"(af[im][0]), "r"(af[im][1]), "r"(af[im][2]), "r"(af[im][3]),
                          "r"(bf[in][0]), "r"(bf[in][1]));
                }
        }
        __syncthreads();
    }

    // epilogue
    float* Yb = Y + (size_t)bz * M * HW;
    const float* Rb = (mode == 2) ? (R + (size_t)bz * M * HW) : nullptr;
    #pragma unroll
    for (int im = 0; im < 2; im++) {
        int mb = m0 + wm * 32 + im * 16;
        #pragma unroll
        for (int half = 0; half < 2; half++) {
            int m = mb + g + half * 8;
            float bv = bias[m];
            #pragma unroll
            for (int in = 0; in < 8; in++) {
                int n = n0 + wn * 64 + in * 8 + t * 2;
                size_t off = (size_t)m * HW + n;
                float v0 = acc[im][in][half * 2 + 0] + bv;
                float v1 = acc[im][in][half * 2 + 1] + bv;
                if (mode == 1) {
                    v0 = 0.5f * v0 * (1.f + erff(v0 * 0.70710678118654752f));
                    v1 = 0.5f * v1 * (1.f + erff(v1 * 0.70710678118654752f));
                } else if (mode == 2) {
                    float2 rv = *(const float2*)&Rb[off];
                    v0 += rv.x; v1 += rv.y;
                }
                *(float2*)&Yb[off] = make_float2(v0, v1);
            }
        }
    }
}

// ---------------- depthwise / grouped 3x3, pad 1 (ic = oc / div) ----------------
__global__ void dwconv3(const float* __restrict__ X, const float* __restrict__ Wt,
                        const float* __restrict__ bias, float* __restrict__ Y,
                        int Cin, int Cout, int div) {
    int p  = blockIdx.x * 256 + threadIdx.x;
    int oc = blockIdx.y;
    int bb = blockIdx.z;
    int xx = p & 127, yy = p >> 7;
    int ic = oc / div;
    const float* Xp = X + ((size_t)bb * Cin + ic) * HW;
    const float* wv = Wt + oc * 9;
    float s = bias[oc];
    #pragma unroll
    for (int dy = -1; dy <= 1; dy++) {
        int y2 = yy + dy;
        if ((unsigned)y2 >= 128u) continue;
        #pragma unroll
        for (int dx = -1; dx <= 1; dx++) {
            int x2 = xx + dx;
            if ((unsigned)x2 >= 128u) continue;
            s += wv[(dy + 1) * 3 + (dx + 1)] * Xp[y2 * 128 + x2];
        }
    }
    Y[((size_t)bb * Cout + oc) * HW + p] = s;
}

// ---------------- per-row inverse L2 norms of (q|k)+prompt ----------------
__global__ void norms_kernel(const float* __restrict__ QKV, const float* __restrict__ prompt) {
    int r  = blockIdx.x;  // 0..383: 0..191 = q rows, 192..383 = k rows
    int bb = blockIdx.y;
    int c = (r < DIM) ? r : (r - DIM);
    int base = (r < DIM) ? 0 : DIM;
    const float* Xp = QKV + ((size_t)bb * C3 + base + c) * HW;
    float pr = prompt[c];
    float s = 0.f;
    for (int n = threadIdx.x; n < HW; n += 256) { float v = Xp[n] + pr; s += v * v; }
    __shared__ float red[256];
    red[threadIdx.x] = s; __syncthreads();
    for (int st = 128; st > 0; st >>= 1) {
        if (threadIdx.x < st) red[threadIdx.x] += red[threadIdx.x + st];
        __syncthreads();
    }
    if (threadIdx.x == 0)
        g_inv[bb * 2 * DIM + r] = 1.f / fmaxf(sqrtf(red[0]), 1e-12f);
}

// ---------------- attn partials: q @ k^T over a 1024-col chunk ----------------
__global__ void attn_qk_kernel(const float* __restrict__ QKV, const float* __restrict__ prompt) {
    int chunk = blockIdx.x;  // 0..15
    int h = blockIdx.y, bb = blockIdx.z;
    __shared__ float qS[CH][65];
    __shared__ float kS[CH][65];
    int tid = threadIdx.x;
    int tx = tid & 15, ty = tid >> 4;
    float acc[3][3] = {};
    const float* Qb = QKV + ((size_t)bb * C3 + h * CH) * HW;
    const float* Kb = QKV + ((size_t)bb * C3 + DIM + h * CH) * HW;
    const float* iq = g_inv + bb * 2 * DIM + h * CH;
    const float* ik = g_inv + bb * 2 * DIM + DIM + h * CH;
    for (int sub = 0; sub < 16; sub++) {
        int n0 = chunk * 1024 + sub * 64;
        for (int i = tid; i < CH * 64; i += 256) {
            int c = i >> 6, n = i & 63;
            float pr = prompt[h * CH + c];
            qS[c][n] = (Qb[(size_t)c * HW + n0 + n] + pr) * iq[c];
            kS[c][n] = (Kb[(size_t)c * HW + n0 + n] + pr) * ik[c];
        }
        __syncthreads();
        #pragma unroll 8
        for (int n = 0; n < 64; n++) {
            float a0 = qS[ty * 3 + 0][n], a1 = qS[ty * 3 + 1][n], a2 = qS[ty * 3 + 2][n];
            float b0 = kS[tx * 3 + 0][n], b1 = kS[tx * 3 + 1][n], b2 = kS[tx * 3 + 2][n];
            acc[0][0] += a0 * b0; acc[0][1] += a0 * b1; acc[0][2] += a0 * b2;
            acc[1][0] += a1 * b0; acc[1][1] += a1 * b1; acc[1][2] += a1 * b2;
            acc[2][0] += a2 * b0; acc[2][1] += a2 * b1; acc[2][2] += a2 * b2;
        }
        __syncthreads();
    }
    float* out = g_attnp + (((size_t)(bb * HEADS + h)) * 16 + chunk) * CH * CH;
    #pragma unroll
    for (int i = 0; i < 3; i++)
        #pragma unroll
        for (int j = 0; j < 3; j++)
            out[(ty * 3 + i) * CH + tx * 3 + j] = acc[i][j];
}

// ---------------- reduce partials, temperature, row softmax ----------------
__global__ void softmax_kernel(const float* __restrict__ temperature) {
    int h = blockIdx.x, bb = blockIdx.y;
    __shared__ float sA[CH][CH];
    const float* P = g_attnp + ((size_t)(bb * HEADS + h)) * 16 * CH * CH;
    float t = temperature[h];
    for (int i = threadIdx.x; i < CH * CH; i += blockDim.x) {
        float s = 0.f;
        #pragma unroll
        for (int c2 = 0; c2 < 16; c2++) s += P[c2 * CH * CH + i];
        sA[i / CH][i % CH] = s * t;
    }
    __syncthreads();
    if (threadIdx.x < CH) {
        int r = threadIdx.x;
        float mx = -1e30f;
        for (int d = 0; d < CH; d++) mx = fmaxf(mx, sA[r][d]);
        float sum = 0.f;
        float e[CH];
        for (int d = 0; d < CH; d++) { e[d] = expf(sA[r][d] - mx); sum += e[d]; }
        float inv = 1.f / sum;
        float* O = g_attn + ((size_t)(bb * HEADS + h)) * CH * CH + r * CH;
        for (int d = 0; d < CH; d++) O[d] = e[d] * inv;
    }
}

// ---------------- out = attn @ (v + prompt) ----------------
__global__ void attn_v_kernel(const float* __restrict__ QKV, const float* __restrict__ prompt,
                              float* __restrict__ O) {
    int nb = blockIdx.x;  // 0..127 (128-col chunks)
    int h = blockIdx.y, bb = blockIdx.z;
    __shared__ float aS[CH][CH];
    __shared__ float vS[CH][128];
    int tid = threadIdx.x;  // 128 threads
    const float* A = g_attn + ((size_t)(bb * HEADS + h)) * CH * CH;
    for (int i = tid; i < CH * CH; i += 128) aS[i / CH][i % CH] = A[i];
    const float* Vb = QKV + ((size_t)bb * C3 + 2 * DIM + h * CH) * HW;
    int n0 = nb * 128;
    for (int i = tid; i < CH * 128; i += 128) {
        int d = i >> 7, n = i & 127;
        vS[d][n] = Vb[(size_t)d * HW + n0 + n] + prompt[h * CH + d];
    }
    __syncthreads();
    float acc[CH];
    #pragma unroll
    for (int c = 0; c < CH; c++) acc[c] = 0.f;
    int n = tid;
    for (int d = 0; d < CH; d++) {
        float vv = vS[d][n];
        #pragma unroll
        for (int c = 0; c < CH; c++) acc[c] += aS[c][d] * vv;
    }
    float* Ob = O + ((size_t)bb * DIM + h * CH) * HW + n0 + n;
    #pragma unroll
    for (int c = 0; c < CH; c++) Ob[(size_t)c * HW] = acc[c];
}

// ---------------- launch ----------------
extern "C" void kernel_launch(void* const* d_in, const int* in_sizes, int n_in,
                              void* d_out, int out_size) {
    const float* x        = (const float*)d_in[0];
    const float* ln1_w    = (const float*)d_in[1];
    const float* ln1_b    = (const float*)d_in[2];
    const float* qkv_w    = (const float*)d_in[3];
    const float* qkv_b    = (const float*)d_in[4];
    const float* qkv_dw_w = (const float*)d_in[5];
    const float* qkv_dw_b = (const float*)d_in[6];
    const float* temp     = (const float*)d_in[7];
    const float* prompt   = (const float*)d_in[8];
    const float* proj_w   = (const float*)d_in[9];
    const float* proj_b   = (const float*)d_in[10];
    const float* ln2_w    = (const float*)d_in[11];
    const float* ln2_b    = (const float*)d_in[12];
    const float* dw1_w    = (const float*)d_in[13];
    const float* dw1_b    = (const float*)d_in[14];
    const float* pm_w     = (const float*)d_in[15];
    const float* pm_b     = (const float*)d_in[16];
    const float* dw2_w    = (const float*)d_in[17];
    const float* dw2_b    = (const float*)d_in[18];
    const float* po_w     = (const float*)d_in[19];
    const float* po_b     = (const float*)d_in[20];
    float* out = (float*)d_out;

    float *bufA, *bufB, *bufC;
    cudaGetSymbolAddress((void**)&bufA, g_bufA);
    cudaGetSymbolAddress((void**)&bufB, g_bufB);
    cudaGetSymbolAddress((void**)&bufC, g_bufC);

    // 1) LN1: x -> bufC
    ln_kernel<<<dim3(HW / 256, BATCH), 256>>>(x, ln1_w, ln1_b, bufC);
    // 2) qkv 1x1 (192->576): bufC -> bufA
    gemm_tc<<<dim3(HW / GBN, C3 / GBM, BATCH), 256>>>(qkv_w, qkv_b, bufC, bufA, C3, DIM, 0, nullptr);
    // 3) qkv depthwise 3x3: bufA -> bufB
    dwconv3<<<dim3(HW / 256, C3, BATCH), 256>>>(bufA, qkv_dw_w, qkv_dw_b, bufB, C3, C3, 1);
    // 4) row norms of q,k (+prompt)
    norms_kernel<<<dim3(2 * DIM, BATCH), 256>>>(bufB, prompt);
    // 5) attn logits partials, softmax, out
    attn_qk_kernel<<<dim3(16, HEADS, BATCH), 256>>>(bufB, prompt);
    softmax_kernel<<<dim3(HEADS, BATCH), 256>>>(temp);
    attn_v_kernel<<<dim3(HW / 128, HEADS, BATCH), 128>>>(bufB, prompt, bufC);
    // 6) proj 1x1 (192->192) + residual x: -> d_out (= x2)
    gemm_tc<<<dim3(HW / GBN, DIM / GBM, BATCH), 256>>>(proj_w, proj_b, bufC, out, DIM, DIM, 2, x);
    // 7) LN2: d_out -> bufC
    ln_kernel<<<dim3(HW / 256, BATCH), 256>>>(out, ln2_w, ln2_b, bufC);
    // 8) grouped 3x3 (192->576, groups=192): bufC -> bufA
    dwconv3<<<dim3(HW / 256, HID, BATCH), 256>>>(bufC, dw1_w, dw1_b, bufA, DIM, HID, 3);
    // 9) pm 1x1 (576->576) + GELU: bufA -> bufB
    gemm_tc<<<dim3(HW / GBN, HID / GBM, BATCH), 256>>>(pm_w, pm_b, bufA, bufB, HID, HID, 1, nullptr);
    // 10) depthwise 3x3 on 576: bufB -> bufA
    dwconv3<<<dim3(HW / 256, HID, BATCH), 256>>>(bufB, dw2_w, dw2_b, bufA, HID, HID, 1);
    // 11) po 1x1 (576->192) + residual (in-place on d_out)
    gemm_tc<<<dim3(HW / GBN, DIM / GBM, BATCH), 256>>>(po_w, po_b, bufA, out, DIM, HID, 2, out);
}

// round 5
// speedup vs baseline: 2.5226x; 1.0540x over previous
#include <cuda_runtime.h>
#include <math.h>

#define BATCH 8
#define DIM   192
#define C3    576
#define HID   576
#define HEADS 4
#define CH    48
#define HW    16384
#define EPSLN 1e-5f

// ---------------- scratch (device globals; allocation-free) ----------------
__device__ float g_bufA[(size_t)BATCH * C3 * HW];   // 302 MB
__device__ float g_bufB[(size_t)BATCH * C3 * HW];   // 302 MB
__device__ float g_bufC[(size_t)BATCH * DIM * HW];  // 100 MB
__device__ float g_inv[BATCH * 2 * DIM];            // 1/||q||, 1/||k|| per row
__device__ float g_attnp[BATCH * HEADS * 16 * CH * CH]; // split-K partials
__device__ float g_attn[BATCH * HEADS * CH * CH];       // softmaxed attn

// ---------------- LayerNorm over channel dim ----------------
__global__ void ln_kernel(const float* __restrict__ x, const float* __restrict__ w,
                          const float* __restrict__ b, float* __restrict__ y) {
    int p  = blockIdx.x * 256 + threadIdx.x;
    int bb = blockIdx.y;
    const float* xp = x + (size_t)bb * DIM * HW + p;
    float s = 0.f, ss = 0.f;
    #pragma unroll 4
    for (int c = 0; c < DIM; c++) { float v = xp[(size_t)c * HW]; s += v; ss += v * v; }
    float mu  = s * (1.f / DIM);
    float var = ss * (1.f / DIM) - mu * mu;
    float inv = rsqrtf(var + EPSLN);
    float* yp = y + (size_t)bb * DIM * HW + p;
    #pragma unroll 4
    for (int c = 0; c < DIM; c++)
        yp[(size_t)c * HW] = (xp[(size_t)c * HW] - mu) * inv * w[c] + b[c];
}

// ---------------- tf32 tensor-core GEMM, cp.async double-buffered ----------------
// Y[m,n] = sum_k W[m,k] X[k,n].  Tile 64x256x32, 256 thr = 8 warps (2m x 4n),
// warp tile 32x64.  mma.sync m16n8k8 tf32 on raw fp32 bits (HW truncation).
// mode 0: +bias, 1: +bias+GELU, 2: +bias+residual.
#define GBM 64
#define GBN 256
#define GBK 32
#define APITCH 36   // 64 rows x 36 floats (144B, 16B aligned, conflict-free: bank=4g+t)
#define BPITCH 260  // 32 rows x 260 floats (1040B, 16B aligned, conflict-free)

struct GemmSmem {
    float As[2][GBM][APITCH];
    float Bs[2][GBK][BPITCH];
};
#define GEMM_SMEM_BYTES ((int)sizeof(GemmSmem))

__device__ __forceinline__ void cp16(float* smem, const float* g) {
    unsigned s = (unsigned)__cvta_generic_to_shared(smem);
    asm volatile("cp.async.ca.shared.global [%0], [%1], 16;\n" :: "r"(s), "l"(g));
}

__global__ __launch_bounds__(256, 2)
void gemm_tc(const float* __restrict__ Wt, const float* __restrict__ bias,
             const float* __restrict__ X, float* __restrict__ Y,
             int M, int K, int mode, const float* __restrict__ R) {
    extern __shared__ char smem_raw[];
    GemmSmem& S = *reinterpret_cast<GemmSmem*>(smem_raw);

    int bz = blockIdx.z;
    int m0 = blockIdx.y * GBM;
    int n0 = blockIdx.x * GBN;
    const float* Xb = X + (size_t)bz * K * HW;

    int tid  = threadIdx.x;
    int warp = tid >> 5;
    int lane = tid & 31;
    int g = lane >> 2;      // 0..7
    int t = lane & 3;       // 0..3
    int wm = warp >> 2;     // 0..1
    int wn = warp & 3;      // 0..3

    // per-thread load coords (fixed across tiles)
    int am  = tid >> 3;            // 0..31 (i adds 32)
    int ak4 = (tid & 7) << 2;
    int bk  = tid >> 6;            // 0..3 (i adds 4)
    int bn4 = (tid & 63) << 2;

    float acc[2][8][4];
    #pragma unroll
    for (int i = 0; i < 2; i++)
        #pragma unroll
        for (int j = 0; j < 8; j++)
            #pragma unroll
            for (int q = 0; q < 4; q++) acc[i][j][q] = 0.f;

    int nIter = K / GBK;

    // prologue: prefetch tile 0 into stage 0
    {
        const float* wsrc = Wt + (size_t)(m0 + am) * K + ak4;
        cp16(&S.As[0][am][ak4],      wsrc);
        cp16(&S.As[0][am + 32][ak4], wsrc + (size_t)32 * K);
        const float* xsrc = Xb + (size_t)bk * HW + n0 + bn4;
        #pragma unroll
        for (int i = 0; i < 8; i++)
            cp16(&S.Bs[0][bk + i * 4][bn4], xsrc + (size_t)(i * 4) * HW);
    }
    asm volatile("cp.async.commit_group;\n");

    int buf = 0;
    for (int it = 0; it < nIter; it++) {
        asm volatile("cp.async.wait_group 0;\n");
        __syncthreads();

        if (it + 1 < nIter) {
            int k0 = (it + 1) * GBK;
            int nb = buf ^ 1;
            const float* wsrc = Wt + (size_t)(m0 + am) * K + k0 + ak4;
            cp16(&S.As[nb][am][ak4],      wsrc);
            cp16(&S.As[nb][am + 32][ak4], wsrc + (size_t)32 * K);
            const float* xsrc = Xb + (size_t)(k0 + bk) * HW + n0 + bn4;
            #pragma unroll
            for (int i = 0; i < 8; i++)
                cp16(&S.Bs[nb][bk + i * 4][bn4], xsrc + (size_t)(i * 4) * HW);
        }
        asm volatile("cp.async.commit_group;\n");

        #pragma unroll
        for (int kk = 0; kk < GBK; kk += 8) {
            unsigned af[2][4], bf[8][2];
            #pragma unroll
            for (int im = 0; im < 2; im++) {
                int rb = wm * 32 + im * 16;
                af[im][0] = __float_as_uint(S.As[buf][rb + g][kk + t]);
                af[im][1] = __float_as_uint(S.As[buf][rb + g + 8][kk + t]);
                af[im][2] = __float_as_uint(S.As[buf][rb + g][kk + t + 4]);
                af[im][3] = __float_as_uint(S.As[buf][rb + g + 8][kk + t + 4]);
            }
            #pragma unroll
            for (int in = 0; in < 8; in++) {
                int cb = wn * 64 + in * 8 + g;
                bf[in][0] = __float_as_uint(S.Bs[buf][kk + t][cb]);
                bf[in][1] = __float_as_uint(S.Bs[buf][kk + t + 4][cb]);
            }
            #pragma unroll
            for (int im = 0; im < 2; im++)
                #pragma unroll
                for (int in = 0; in < 8; in++) {
                    asm volatile(
                        "mma.sync.aligned.m16n8k8.row.col.f32.tf32.tf32.f32 "
                        "{%0,%1,%2,%3}, {%4,%5,%6,%7}, {%8,%9}, {%0,%1,%2,%3};"
                        : "+f"(acc[im][in][0]), "+f"(acc[im][in][1]),
                          "+f"(acc[im][in][2]), "+f"(acc[im][in][3])
                        : "r"(af[im][0]), "r"(af[im][1]), "r"(af[im][2]), "r"(af[im][3]),
                          "r"(bf[in][0]), "r"(bf[in][1]));
                }
        }
        __syncthreads();
        buf ^= 1;
    }

    // epilogue
    float* Yb = Y + (size_t)bz * M * HW;
    const float* Rb = (mode == 2) ? (R + (size_t)bz * M * HW) : nullptr;
    #pragma unroll
    for (int im = 0; im < 2; im++) {
        int mb = m0 + wm * 32 + im * 16;
        #pragma unroll
        for (int half = 0; half < 2; half++) {
            int m = mb + g + half * 8;
            float bv = bias[m];
            #pragma unroll
            for (int in = 0; in < 8; in++) {
                int n = n0 + wn * 64 + in * 8 + t * 2;
                size_t off = (size_t)m * HW + n;
                float v0 = acc[im][in][half * 2 + 0] + bv;
                float v1 = acc[im][in][half * 2 + 1] + bv;
                if (mode == 1) {
                    v0 = 0.5f * v0 * (1.f + erff(v0 * 0.70710678118654752f));
                    v1 = 0.5f * v1 * (1.f + erff(v1 * 0.70710678118654752f));
                } else if (mode == 2) {
                    float2 rv = *(const float2*)&Rb[off];
                    v0 += rv.x; v1 += rv.y;
                }
                *(float2*)&Yb[off] = make_float2(v0, v1);
            }
        }
    }
}

// ---------------- depthwise / grouped 3x3, pad 1 (ic = oc / div) ----------------
__global__ void dwconv3(const float* __restrict__ X, const float* __restrict__ Wt,
                        const float* __restrict__ bias, float* __restrict__ Y,
                        int Cin, int Cout, int div) {
    int p  = blockIdx.x * 256 + threadIdx.x;
    int oc = blockIdx.y;
    int bb = blockIdx.z;
    int xx = p & 127, yy = p >> 7;
    int ic = oc / div;
    const float* Xp = X + ((size_t)bb * Cin + ic) * HW;
    const float* wv = Wt + oc * 9;
    float s = bias[oc];
    #pragma unroll
    for (int dy = -1; dy <= 1; dy++) {
        int y2 = yy + dy;
        if ((unsigned)y2 >= 128u) continue;
        #pragma unroll
        for (int dx = -1; dx <= 1; dx++) {
            int x2 = xx + dx;
            if ((unsigned)x2 >= 128u) continue;
            s += wv[(dy + 1) * 3 + (dx + 1)] * Xp[y2 * 128 + x2];
        }
    }
    Y[((size_t)bb * Cout + oc) * HW + p] = s;
}

// ---------------- per-row inverse L2 norms of (q|k)+prompt ----------------
__global__ void norms_kernel(const float* __restrict__ QKV, const float* __restrict__ prompt) {
    int r  = blockIdx.x;  // 0..383: 0..191 = q rows, 192..383 = k rows
    int bb = blockIdx.y;
    int c = (r < DIM) ? r : (r - DIM);
    int base = (r < DIM) ? 0 : DIM;
    const float* Xp = QKV + ((size_t)bb * C3 + base + c) * HW;
    float pr = prompt[c];
    float s = 0.f;
    for (int n = threadIdx.x; n < HW; n += 256) { float v = Xp[n] + pr; s += v * v; }
    __shared__ float red[256];
    red[threadIdx.x] = s; __syncthreads();
    for (int st = 128; st > 0; st >>= 1) {
        if (threadIdx.x < st) red[threadIdx.x] += red[threadIdx.x + st];
        __syncthreads();
    }
    if (threadIdx.x == 0)
        g_inv[bb * 2 * DIM + r] = 1.f / fmaxf(sqrtf(red[0]), 1e-12f);
}

// ---------------- attn partials: q @ k^T over a 1024-col chunk ----------------
__global__ void attn_qk_kernel(const float* __restrict__ QKV, const float* __restrict__ prompt) {
    int chunk = blockIdx.x;  // 0..15
    int h = blockIdx.y, bb = blockIdx.z;
    __shared__ float qS[CH][65];
    __shared__ float kS[CH][65];
    int tid = threadIdx.x;
    int tx = tid & 15, ty = tid >> 4;
    float acc[3][3] = {};
    const float* Qb = QKV + ((size_t)bb * C3 + h * CH) * HW;
    const float* Kb = QKV + ((size_t)bb * C3 + DIM + h * CH) * HW;
    const float* iq = g_inv + bb * 2 * DIM + h * CH;
    const float* ik = g_inv + bb * 2 * DIM + DIM + h * CH;
    for (int sub = 0; sub < 16; sub++) {
        int n0 = chunk * 1024 + sub * 64;
        for (int i = tid; i < CH * 64; i += 256) {
            int c = i >> 6, n = i & 63;
            float pr = prompt[h * CH + c];
            qS[c][n] = (Qb[(size_t)c * HW + n0 + n] + pr) * iq[c];
            kS[c][n] = (Kb[(size_t)c * HW + n0 + n] + pr) * ik[c];
        }
        __syncthreads();
        #pragma unroll 8
        for (int n = 0; n < 64; n++) {
            float a0 = qS[ty * 3 + 0][n], a1 = qS[ty * 3 + 1][n], a2 = qS[ty * 3 + 2][n];
            float b0 = kS[tx * 3 + 0][n], b1 = kS[tx * 3 + 1][n], b2 = kS[tx * 3 + 2][n];
            acc[0][0] += a0 * b0; acc[0][1] += a0 * b1; acc[0][2] += a0 * b2;
            acc[1][0] += a1 * b0; acc[1][1] += a1 * b1; acc[1][2] += a1 * b2;
            acc[2][0] += a2 * b0; acc[2][1] += a2 * b1; acc[2][2] += a2 * b2;
        }
        __syncthreads();
    }
    float* out = g_attnp + (((size_t)(bb * HEADS + h)) * 16 + chunk) * CH * CH;
    #pragma unroll
    for (int i = 0; i < 3; i++)
        #pragma unroll
        for (int j = 0; j < 3; j++)
            out[(ty * 3 + i) * CH + tx * 3 + j] = acc[i][j];
}

// ---------------- reduce partials, temperature, row softmax ----------------
__global__ void softmax_kernel(const float* __restrict__ temperature) {
    int h = blockIdx.x, bb = blockIdx.y;
    __shared__ float sA[CH][CH];
    const float* P = g_attnp + ((size_t)(bb * HEADS + h)) * 16 * CH * CH;
    float t = temperature[h];
    for (int i = threadIdx.x; i < CH * CH; i += blockDim.x) {
        float s = 0.f;
        #pragma unroll
        for (int c2 = 0; c2 < 16; c2++) s += P[c2 * CH * CH + i];
        sA[i / CH][i % CH] = s * t;
    }
    __syncthreads();
    if (threadIdx.x < CH) {
        int r = threadIdx.x;
        float mx = -1e30f;
        for (int d = 0; d < CH; d++) mx = fmaxf(mx, sA[r][d]);
        float sum = 0.f;
        float e[CH];
        for (int d = 0; d < CH; d++) { e[d] = expf(sA[r][d] - mx); sum += e[d]; }
        float inv = 1.f / sum;
        float* O = g_attn + ((size_t)(bb * HEADS + h)) * CH * CH + r * CH;
        for (int d = 0; d < CH; d++) O[d] = e[d] * inv;
    }
}

// ---------------- out = attn @ (v + prompt) ----------------
__global__ void attn_v_kernel(const float* __restrict__ QKV, const float* __restrict__ prompt,
                              float* __restrict__ O) {
    int nb = blockIdx.x;  // 0..127 (128-col chunks)
    int h = blockIdx.y, bb = blockIdx.z;
    __shared__ float aS[CH][CH];
    __shared__ float vS[CH][128];
    int tid = threadIdx.x;  // 128 threads
    const float* A = g_attn + ((size_t)(bb * HEADS + h)) * CH * CH;
    for (int i = tid; i < CH * CH; i += 128) aS[i / CH][i % CH] = A[i];
    const float* Vb = QKV + ((size_t)bb * C3 + 2 * DIM + h * CH) * HW;
    int n0 = nb * 128;
    for (int i = tid; i < CH * 128; i += 128) {
        int d = i >> 7, n = i & 127;
        vS[d][n] = Vb[(size_t)d * HW + n0 + n] + prompt[h * CH + d];
    }
    __syncthreads();
    float acc[CH];
    #pragma unroll
    for (int c = 0; c < CH; c++) acc[c] = 0.f;
    int n = tid;
    for (int d = 0; d < CH; d++) {
        float vv = vS[d][n];
        #pragma unroll
        for (int c = 0; c < CH; c++) acc[c] += aS[c][d] * vv;
    }
    float* Ob = O + ((size_t)bb * DIM + h * CH) * HW + n0 + n;
    #pragma unroll
    for (int c = 0; c < CH; c++) Ob[(size_t)c * HW] = acc[c];
}

// ---------------- launch ----------------
extern "C" void kernel_launch(void* const* d_in, const int* in_sizes, int n_in,
                              void* d_out, int out_size) {
    const float* x        = (const float*)d_in[0];
    const float* ln1_w    = (const float*)d_in[1];
    const float* ln1_b    = (const float*)d_in[2];
    const float* qkv_w    = (const float*)d_in[3];
    const float* qkv_b    = (const float*)d_in[4];
    const float* qkv_dw_w = (const float*)d_in[5];
    const float* qkv_dw_b = (const float*)d_in[6];
    const float* temp     = (const float*)d_in[7];
    const float* prompt   = (const float*)d_in[8];
    const float* proj_w   = (const float*)d_in[9];
    const float* proj_b   = (const float*)d_in[10];
    const float* ln2_w    = (const float*)d_in[11];
    const float* ln2_b    = (const float*)d_in[12];
    const float* dw1_w    = (const float*)d_in[13];
    const float* dw1_b    = (const float*)d_in[14];
    const float* pm_w     = (const float*)d_in[15];
    const float* pm_b     = (const float*)d_in[16];
    const float* dw2_w    = (const float*)d_in[17];
    const float* dw2_b    = (const float*)d_in[18];
    const float* po_w     = (const float*)d_in[19];
    const float* po_b     = (const float*)d_in[20];
    float* out = (float*)d_out;

    float *bufA, *bufB, *bufC;
    cudaGetSymbolAddress((void**)&bufA, g_bufA);
    cudaGetSymbolAddress((void**)&bufB, g_bufB);
    cudaGetSymbolAddress((void**)&bufC, g_bufC);

    cudaFuncSetAttribute(gemm_tc, cudaFuncAttributeMaxDynamicSharedMemorySize,
                         GEMM_SMEM_BYTES);

    // 1) LN1: x -> bufC
    ln_kernel<<<dim3(HW / 256, BATCH), 256>>>(x, ln1_w, ln1_b, bufC);
    // 2) qkv 1x1 (192->576): bufC -> bufA
    gemm_tc<<<dim3(HW / GBN, C3 / GBM, BATCH), 256, GEMM_SMEM_BYTES>>>(
        qkv_w, qkv_b, bufC, bufA, C3, DIM, 0, nullptr);
    // 3) qkv depthwise 3x3: bufA -> bufB
    dwconv3<<<dim3(HW / 256, C3, BATCH), 256>>>(bufA, qkv_dw_w, qkv_dw_b, bufB, C3, C3, 1);
    // 4) row norms of q,k (+prompt)
    norms_kernel<<<dim3(2 * DIM, BATCH), 256>>>(bufB, prompt);
    // 5) attn logits partials, softmax, out
    attn_qk_kernel<<<dim3(16, HEADS, BATCH), 256>>>(bufB, prompt);
    softmax_kernel<<<dim3(HEADS, BATCH), 256>>>(temp);
    attn_v_kernel<<<dim3(HW / 128, HEADS, BATCH), 128>>>(bufB, prompt, bufC);
    // 6) proj 1x1 (192->192) + residual x: -> d_out (= x2)
    gemm_tc<<<dim3(HW / GBN, DIM / GBM, BATCH), 256, GEMM_SMEM_BYTES>>>(
        proj_w, proj_b, bufC, out, DIM, DIM, 2, x);
    // 7) LN2: d_out -> bufC
    ln_kernel<<<dim3(HW / 256, BATCH), 256>>>(out, ln2_w, ln2_b, bufC);
    // 8) grouped 3x3 (192->576, groups=192): bufC -> bufA
    dwconv3<<<dim3(HW / 256, HID, BATCH), 256>>>(bufC, dw1_w, dw1_b, bufA, DIM, HID, 3);
    // 9) pm 1x1 (576->576) + GELU: bufA -> bufB
    gemm_tc<<<dim3(HW / GBN, HID / GBM, BATCH), 256, GEMM_SMEM_BYTES>>>(
        pm_w, pm_b, bufA, bufB, HID, HID, 1, nullptr);
    // 10) depthwise 3x3 on 576: bufB -> bufA
    dwconv3<<<dim3(HW / 256, HID, BATCH), 256>>>(bufB, dw2_w, dw2_b, bufA, HID, HID, 1);
    // 11) po 1x1 (576->192) + residual (in-place on d_out)
    gemm_tc<<<dim3(HW / GBN, DIM / GBM, BATCH), 256, GEMM_SMEM_BYTES>>>(
        po_w, po_b, bufA, out, DIM, HID, 2, out);
}